// round 7
// baseline (speedup 1.0000x reference)
#include <cuda_runtime.h>

#define B_      32
#define T_      512
#define D_      384
#define MAXOUT  3584                    // T_ * (8 - 1)
#define VEC     (D_ / 4)                // 96 float4 per row
#define THREADS 512                     // 16 warps
#define FRAMES_PER_TILE 16              // one frame per warp
#define SCATTER_TILES (T_ / FRAMES_PER_TILE)     // 32
#define ZROWS   128                     // output rows per zero tile
#define ZERO_TILES (MAXOUT / ZROWS)              // 28
#define TILES_X (SCATTER_TILES + ZERO_TILES)     // 60

// Scatter formulation: source frame -> dur consecutive output rows.
// blockIdx.x < SCATTER_TILES : scatter tile (16 frames, one per warp)
// blockIdx.x >= SCATTER_TILES: zero tile (fills rows >= total in its range)
// The two row sets are disjoint (scatter writes rows < total only), no race.
__global__ void __launch_bounds__(THREADS) lr_scatter_kernel(
    const int*    __restrict__ dur,
    const float4* __restrict__ in,
    float4*       __restrict__ out)
{
    __shared__ int s_cum[T_];
    __shared__ int s_d[T_];
    __shared__ int wsum[16];

    const int tid  = threadIdx.x;
    const int b    = blockIdx.y;
    const int lane = tid & 31;
    const int warp = tid >> 5;

    // ── Block-wide inclusive scan of this batch's 512 durations ──
    int d = max(dur[b * T_ + tid], 0);
    int v = d;
    #pragma unroll
    for (int o = 1; o < 32; o <<= 1) {
        int n = __shfl_up_sync(0xffffffffu, v, o);
        if (lane >= o) v += n;
    }
    if (lane == 31) wsum[warp] = v;
    __syncthreads();
    if (warp == 0) {
        int w = (lane < 16) ? wsum[lane] : 0;
        #pragma unroll
        for (int o = 1; o < 16; o <<= 1) {
            int n = __shfl_up_sync(0xffffffffu, w, o);
            if (lane >= o) w += n;
        }
        if (lane < 16) wsum[lane] = w;
    }
    __syncthreads();

    const int incl = v + (warp > 0 ? wsum[warp - 1] : 0);
    s_cum[tid] = incl;
    s_d[tid]   = d;
    __syncthreads();

    const int total = s_cum[T_ - 1];

    const float4* __restrict__ inb  = in  + b * (T_ * VEC);
    float4*       __restrict__ outb = out + b * (MAXOUT * VEC);

    if (blockIdx.x < SCATTER_TILES) {
        // ── Scatter: warp w owns frame t; copies its row dur[t] times ──
        const int t  = blockIdx.x * FRAMES_PER_TILE + warp;
        const int dt = s_d[t];
        if (dt == 0) return;
        const int start = s_cum[t] - dt;

        // Load the 1536B source row: 3 coalesced LDG.128 per lane.
        const float4* src = inb + t * VEC;
        const float4 v0 = __ldg(&src[lane]);
        const float4 v1 = __ldg(&src[lane + 32]);
        const float4 v2 = __ldg(&src[lane + 64]);

        // Fire-and-forget stores: dur-uniform per warp, each STG.128 512B coalesced.
        #pragma unroll 4
        for (int r = 0; r < dt; ++r) {
            float4* dst = outb + (start + r) * VEC;
            __stcs(&dst[lane],      v0);
            __stcs(&dst[lane + 32], v1);
            __stcs(&dst[lane + 64], v2);
        }
    } else {
        // ── Zero fill: rows [max(lo, total), hi) of this tile ──
        const int zx = blockIdx.x - SCATTER_TILES;
        const int lo = max(zx * ZROWS, total);
        const int hi = (zx + 1) * ZROWS;
        if (lo >= hi) return;

        const float4 z = make_float4(0.f, 0.f, 0.f, 0.f);
        const int f4_lo = lo * VEC;
        const int f4_hi = hi * VEC;
        for (int i = f4_lo + tid; i < f4_hi; i += THREADS)
            __stcs(&outb[i], z);
    }
}

extern "C" void kernel_launch(void* const* d_in, const int* in_sizes, int n_in,
                              void* d_out, int out_size)
{
    const float* x   = (const float*)d_in[0];   // [B, T, D] float32
    const int*   dur = (const int*)d_in[1];     // [B, T] int32
    float* out = (float*)d_out;                 // [B, MAXOUT, D] float32

    dim3 grid(TILES_X, B_);
    lr_scatter_kernel<<<grid, THREADS>>>(dur, (const float4*)x, (float4*)out);
}